// round 16
// baseline (speedup 1.0000x reference)
#include <cuda_runtime.h>
#include <cuda_bf16.h>

#define S_DIM 128
#define A_DIM 96
#define B_DIM 256
#define LX    512
#define LY    256
#define XOFF_STRIDE 584   // padded clamped xs byte-offset table per batch

// Per-batch gathered cost table: Gt[b][x][j] = (-softmax(P)[x] - 1)[ys[b][j]]
__device__ float g_Gt[(size_t)B_DIM * S_DIM * LY];
// xoff[b][t] = xs[b][clamp(t-32, 0, xl-1)] * 1024  (byte row offset in Gt)
__device__ int   g_xoff[B_DIM * XOFF_STRIDE];

// Fused prep: grid 128, block x
//  - warp 0 computes softmax row x (c'' = -softmax - 1) into smem
//  - all 256 threads scatter row x into every batch's Gt slice (coalesced)
//  - block x also builds xoff for batches 2x and 2x+1
// One launch instead of softmax_neg + build: removes the 4.5us launch-bound
// softmax kernel; softmax work rides along at 1 row/block with zero redundancy.
__global__ void prep_kernel(const float* __restrict__ P,
                            const int* __restrict__ xs,
                            const int* __restrict__ ys,
                            const int* __restrict__ xlen) {
    __shared__ float sc[A_DIM];
    const int x   = blockIdx.x;
    const int tid = threadIdx.x;

    if (tid < 32) {
        const float* pr = P + x * A_DIM;
        float v0 = pr[tid], v1 = pr[tid + 32], v2 = pr[tid + 64];
        float m = fmaxf(v0, fmaxf(v1, v2));
        #pragma unroll
        for (int o = 16; o > 0; o >>= 1) m = fmaxf(m, __shfl_xor_sync(0xffffffffu, m, o));
        float e0 = expf(v0 - m), e1 = expf(v1 - m), e2 = expf(v2 - m);
        float s = e0 + e1 + e2;
        #pragma unroll
        for (int o = 16; o > 0; o >>= 1) s += __shfl_xor_sync(0xffffffffu, s, o);
        float inv = -1.0f / s;
        sc[tid     ] = e0 * inv - 1.0f;
        sc[tid + 32] = e1 * inv - 1.0f;
        sc[tid + 64] = e2 * inv - 1.0f;
    }

    // xoff for batches 2x and 2x+1 (independent of sc)
    #pragma unroll
    for (int u = tid; u < 2 * XOFF_STRIDE; u += 256) {
        const int half = (u >= XOFF_STRIDE) ? 1 : 0;
        const int bb   = 2 * x + half;
        const int t    = u - half * XOFF_STRIDE;
        const int xl   = xlen[bb] - 1;
        const int v    = min(max(t - 32, 0), xl - 1);
        g_xoff[bb * XOFF_STRIDE + t] = xs[(size_t)bb * LX + v] * (LY * 4);
    }
    __syncthreads();

    // scatter row x into all batches: Gt[bb][x][tid] = sc[ys[bb][tid]]
    float*      gt  = g_Gt + (size_t)x * LY + tid;
    const int*  ysp = ys + tid;
    #pragma unroll 4
    for (int bb = 0; bb < B_DIM; ++bb)
        gt[(size_t)bb * (S_DIM * LY)] = sc[ysp[(size_t)bb * LY]];
}

// One warp per batch (256 x 1-warp blocks), lane-skewed wavefront,
// D'' = D - j - r space  (byte-identical to the proven 47.6us R15 dp kernel).
//   E''[j]   = min(D''_{r-1}[j], D''_{r-1}[j-1] + c'')
//   D''_r[j] = min(B, E''[8L+1..j])   B = D''_r[8L] (shfl; lane0: 0)
// Prefix via Brent-Kung min-scan with carry-in B: 14 FMNMX, B->D[7] depth 2.

#define DP_CORE(a, bv, NA, NB, xo_, COMMIT) do {                               \
    const char* rp_ = Gtb + (xo_);                                             \
    float4 nA_ = *(const float4*)rp_;                                          \
    float4 nB_ = *(const float4*)(rp_ + 16);                                   \
    float B_ = is0 ? 0.0f : Dl;                                                \
    float E0_ = fminf(D[0], bprev + (a).x);                                    \
    float E1_ = fminf(D[1], D[0] + (a).y);                                     \
    float E2_ = fminf(D[2], D[1] + (a).z);                                     \
    float E3_ = fminf(D[3], D[2] + (a).w);                                     \
    float E4_ = fminf(D[4], D[3] + (bv).x);                                    \
    float E5_ = fminf(D[5], D[4] + (bv).y);                                    \
    float E6_ = fminf(D[6], D[5] + (bv).z);                                    \
    float E7_ = fminf(D[7], D[6] + (bv).w);                                    \
    float a1_ = fminf(E0_, E1_);                                               \
    float a2_ = fminf(E2_, E3_);                                               \
    float a3_ = fminf(E4_, E5_);                                               \
    float a4_ = fminf(E6_, E7_);                                               \
    float b1_ = fminf(a1_, a2_);                                               \
    float b2_ = fminf(a3_, a4_);                                               \
    float n0_ = fminf(B_, E0_);                                                \
    float n1_ = fminf(B_, a1_);                                                \
    float n2_ = fminf(n1_, E2_);                                               \
    float n3_ = fminf(B_, b1_);                                                \
    float n4_ = fminf(n3_, E4_);                                               \
    float n5_ = fminf(n3_, a3_);                                               \
    float n6_ = fminf(n5_, E6_);                                               \
    float n7_ = fminf(n3_, b2_);                                               \
    if (COMMIT) {                                                              \
        D[0] = n0_; D[1] = n1_; D[2] = n2_; D[3] = n3_;                        \
        D[4] = n4_; D[5] = n5_; D[6] = n6_; D[7] = n7_;                        \
    }                                                                          \
    float sh_ = __shfl_up_sync(0xffffffffu, D[7], 1);                          \
    bprev = B_;                                                                \
    Dl    = sh_;                                                               \
    (NA) = nA_;  (NB) = nB_;                                                   \
} while (0)

#define DP_STEP_ROT(COMMIT) do {                                               \
    int xor_ = xo[0];                                                          \
    float4 rA_, rB_;                                                           \
    DP_CORE(cA[0], cB[0], rA_, rB_, xor_, COMMIT);                             \
    cA[0] = cA[1]; cA[1] = cA[2]; cA[2] = cA[3]; cA[3] = rA_;                  \
    cB[0] = cB[1]; cB[1] = cB[2]; cB[2] = cB[3]; cB[3] = rB_;                  \
    xo[0] = xo[1]; xo[1] = xo[2]; xo[2] = xo[3]; xo[3] = *xpr; ++xpr;          \
} while (0)

#define DP_STEP_PH(p) do {                                                     \
    DP_CORE(cA[p], cB[p], cA[p], cB[p], xo[p], true);                          \
    xo[p] = xpr[p];                                                            \
} while (0)

__global__ void __launch_bounds__(32, 4) dp_kernel(
    const int* __restrict__ xlen,
    const int* __restrict__ ylen,
    float* __restrict__ out)
{
    const int b    = blockIdx.x;
    const int lane = threadIdx.x;
    const int xl   = xlen[b] - 1;   // target row (1..511)
    const int yl   = ylen[b] - 1;   // target col (1..255)

    const char* Gtb = (const char*)(g_Gt + (size_t)b * S_DIM * LY) + lane * 32;
    const int*  xpb = g_xoff + b * XOFF_STRIDE;

    const int t_lane = (yl - 1) >> 3;
    const int k_t    = (yl - 1) & 7;
    const int s_end  = xl + t_lane;
    const bool is0   = (lane == 0);

    float D[8];
    #pragma unroll
    for (int k = 0; k < 8; ++k) D[k] = 0.0f;   // row 0: D'' = 0

    float Dl = 0.0f, bprev = 0.0f;

    // prefill: step sigma uses xoff idx sigma + 31 - lane
    float4 cA[4], cB[4];
    #pragma unroll
    for (int p = 0; p < 4; ++p) {
        int xv = xpb[32 - lane + p];            // steps 1..4
        const char* r = Gtb + xv;
        cA[p] = *(const float4*)r;
        cB[p] = *(const float4*)(r + 16);
    }
    int xo[4];
    #pragma unroll
    for (int p = 0; p < 4; ++p) xo[p] = xpb[36 - lane + p];   // steps 5..8
    const int* xpr = xpb + 40 - lane;           // steps 9.. (prefetch feed)

    // ---- ramp-in: freeze predicate live, rotating buffers ----
    int s = 1;
    const int rampEnd = min(31, s_end);
    for (; s <= rampEnd; ++s) {
        const bool act = (s > lane);
        DP_STEP_ROT(act);
    }

    // ---- steady: hand-unrolled x4, literal phases, no rotations ----
    int nSteady = s_end - s + 1;
    int n4      = nSteady & ~3;
    const int* xq_end = xpr + n4;
    for (; xpr != xq_end; xpr += 4) {
        DP_STEP_PH(0);
        DP_STEP_PH(1);
        DP_STEP_PH(2);
        DP_STEP_PH(3);
    }
    s += n4;

    // ---- remainder (<=3 steps), rotating ----
    for (; s <= s_end; ++s) {
        DP_STEP_ROT(true);
    }

    if (lane == t_lane) out[b] = D[k_t] + (float)(xl + yl);
}

extern "C" void kernel_launch(void* const* d_in, const int* in_sizes, int n_in,
                              void* d_out, int out_size) {
    const float* P    = (const float*)d_in[0];
    const int*   xs   = (const int*)d_in[1];
    const int*   ys   = (const int*)d_in[2];
    const int*   xlen = (const int*)d_in[3];
    const int*   ylen = (const int*)d_in[4];
    float*       out  = (float*)d_out;

    prep_kernel<<<S_DIM, 256>>>(P, xs, ys, xlen);
    dp_kernel<<<B_DIM, 32>>>(xlen, ylen, out);
}

// round 17
// speedup vs baseline: 1.1276x; 1.1276x over previous
#include <cuda_runtime.h>
#include <cuda_bf16.h>

#define S_DIM 128
#define A_DIM 96
#define B_DIM 256
#define LX    512
#define LY    256
#define XOFF_STRIDE 584   // padded clamped xs byte-offset table per batch

// g_Cn[s][a] = -softmax(P,axis=1)[s][a] - 1   (c'' for D'' space)
__device__ float g_Cn[S_DIM * A_DIM];
// Per-batch gathered cost table: Gt[b][x][j] = g_Cn[x][ys[b][j]]
__device__ float g_Gt[(size_t)B_DIM * S_DIM * LY];
// xoff[b][t] = xs[b][clamp(t-32, 0, xl-1)] * 1024  (byte row offset in Gt)
__device__ int   g_xoff[B_DIM * XOFF_STRIDE];

__global__ void softmax_neg_kernel(const float* __restrict__ P) {
    int row  = blockIdx.x;
    int lane = threadIdx.x;
    const float* pr = P + row * A_DIM;
    float v0 = pr[lane], v1 = pr[lane + 32], v2 = pr[lane + 64];
    float m = fmaxf(v0, fmaxf(v1, v2));
    #pragma unroll
    for (int o = 16; o > 0; o >>= 1) m = fmaxf(m, __shfl_xor_sync(0xffffffffu, m, o));
    float e0 = expf(v0 - m), e1 = expf(v1 - m), e2 = expf(v2 - m);
    float s = e0 + e1 + e2;
    #pragma unroll
    for (int o = 16; o > 0; o >>= 1) s += __shfl_xor_sync(0xffffffffu, s, o);
    float inv = -1.0f / s;
    g_Cn[row * A_DIM + lane     ] = e0 * inv - 1.0f;
    g_Cn[row * A_DIM + lane + 32] = e1 * inv - 1.0f;
    g_Cn[row * A_DIM + lane + 64] = e2 * inv - 1.0f;
}

// One block per batch: build Gt[b] (gather through smem) and xoff[b].
__global__ void build_kernel(const int* __restrict__ xs,
                             const int* __restrict__ ys,
                             const int* __restrict__ xlen) {
    __shared__ float sC[S_DIM * A_DIM];
    const int b   = blockIdx.x;
    const int tid = threadIdx.x;

    {   // stage cost table (12288 floats = 3072 float4)
        const float4* src = (const float4*)g_Cn;
        float4*       dst = (float4*)sC;
        #pragma unroll
        for (int i = tid; i < (S_DIM * A_DIM) / 4; i += 256) dst[i] = src[i];
    }

    const int xl   = xlen[b] - 1;
    const int xcap = xl - 1;
    const int* xsb = xs + (size_t)b * LX;
    for (int t = tid; t < XOFF_STRIDE; t += 256) {
        int q = t - 32;
        int v = min(max(q, 0), xcap);
        g_xoff[b * XOFF_STRIDE + t] = xsb[v] * (LY * 4);
    }
    __syncthreads();

    const int yj = ys[(size_t)b * LY + tid];
    float* ob = g_Gt + (size_t)b * S_DIM * LY + tid;
    #pragma unroll 4
    for (int x = 0; x < S_DIM; ++x)
        ob[x * LY] = sC[x * A_DIM + yj];
}

// One warp per batch (256 x 1-warp blocks), lane-skewed wavefront,
// D'' = D - j - r space. Brent-Kung min-scan with carry-in B (R15-proven).
// Depth-2 cost pipeline (2 float4 pairs), xoff loaded directly in prefetch:
// minimal live registers in the hot loop.
//   E''[j]   = min(D''_{r-1}[j], D''_{r-1}[j-1] + c'')
//   D''_r[j] = min(B, E''[8L+1..j])   B = D''_r[8L] (shfl; lane0: 0)

#define DP_CORE(a, bv, COMMIT) do {                                            \
    /* prefetch costs for step s+2; xoff loaded inline (L1-resident) */        \
    int xo_ = *xpr; ++xpr;                                                     \
    const char* rp_ = Gtb + xo_;                                               \
    float4 nA_ = *(const float4*)rp_;                                          \
    float4 nB_ = *(const float4*)(rp_ + 16);                                   \
    float B_ = is0 ? 0.0f : Dl;                                                \
    float E0_ = fminf(D[0], bprev + (a).x);                                    \
    float E1_ = fminf(D[1], D[0] + (a).y);                                     \
    float E2_ = fminf(D[2], D[1] + (a).z);                                     \
    float E3_ = fminf(D[3], D[2] + (a).w);                                     \
    float E4_ = fminf(D[4], D[3] + (bv).x);                                    \
    float E5_ = fminf(D[5], D[4] + (bv).y);                                    \
    float E6_ = fminf(D[6], D[5] + (bv).z);                                    \
    float E7_ = fminf(D[7], D[6] + (bv).w);                                    \
    float a1_ = fminf(E0_, E1_);                                               \
    float a2_ = fminf(E2_, E3_);                                               \
    float a3_ = fminf(E4_, E5_);                                               \
    float a4_ = fminf(E6_, E7_);                                               \
    float b1_ = fminf(a1_, a2_);                                               \
    float b2_ = fminf(a3_, a4_);                                               \
    float n0_ = fminf(B_, E0_);                                                \
    float n1_ = fminf(B_, a1_);                                                \
    float n2_ = fminf(n1_, E2_);                                               \
    float n3_ = fminf(B_, b1_);                                                \
    float n4_ = fminf(n3_, E4_);                                               \
    float n5_ = fminf(n3_, a3_);                                               \
    float n6_ = fminf(n5_, E6_);                                               \
    float n7_ = fminf(n3_, b2_);                                               \
    if (COMMIT) {                                                              \
        D[0] = n0_; D[1] = n1_; D[2] = n2_; D[3] = n3_;                        \
        D[4] = n4_; D[5] = n5_; D[6] = n6_; D[7] = n7_;                        \
    }                                                                          \
    float sh_ = __shfl_up_sync(0xffffffffu, D[7], 1);                          \
    bprev = B_;                                                                \
    Dl    = sh_;                                                               \
    (a) = nA_;  (bv) = nB_;                                                    \
} while (0)

__global__ void __launch_bounds__(32, 4) dp_kernel(
    const int* __restrict__ xlen,
    const int* __restrict__ ylen,
    float* __restrict__ out)
{
    const int b    = blockIdx.x;
    const int lane = threadIdx.x;
    const int xl   = xlen[b] - 1;   // target row (1..511)
    const int yl   = ylen[b] - 1;   // target col (1..255)

    const char* Gtb = (const char*)(g_Gt + (size_t)b * S_DIM * LY) + lane * 32;
    const int*  xpb = g_xoff + b * XOFF_STRIDE;

    const int t_lane = (yl - 1) >> 3;
    const int k_t    = (yl - 1) & 7;
    const int s_end  = xl + t_lane;
    const bool is0   = (lane == 0);

    float D[8];
    #pragma unroll
    for (int k = 0; k < 8; ++k) D[k] = 0.0f;   // row 0: D'' = 0

    float Dl = 0.0f, bprev = 0.0f;

    // prefill slots for steps 1 and 2 (step sigma uses xoff idx sigma+31-lane)
    float4 cA0, cB0, cA1, cB1;
    {
        const char* r0 = Gtb + xpb[32 - lane];
        cA0 = *(const float4*)r0;
        cB0 = *(const float4*)(r0 + 16);
        const char* r1 = Gtb + xpb[33 - lane];
        cA1 = *(const float4*)r1;
        cB1 = *(const float4*)(r1 + 16);
    }
    const int* xpr = xpb + 34 - lane;   // at step s: *xpr = idx (s+2)+31-lane

    if (s_end >= 32) {
        // ---- ramp: steps 1..32 in pairs, freeze predicate live ----
        int s = 1;
        #pragma unroll 2
        for (; s <= 32; s += 2) {
            { const bool act = (s     > lane); DP_CORE(cA0, cB0, act); }
            { const bool act = (s + 1 > lane); DP_CORE(cA1, cB1, act); }
        }
        // ---- steady: pairs, no predicate ----
        for (; s + 1 <= s_end; s += 2) {
            DP_CORE(cA0, cB0, true);
            DP_CORE(cA1, cB1, true);
        }
        // ---- leftover (parity preserved: consumes slot 0) ----
        if (s <= s_end) { DP_CORE(cA0, cB0, true); }
    } else {
        // tiny-batch fallback (s_end <= 31), rare
        for (int s = 1; s <= s_end; ++s) {
            const bool act = (s > lane);
            if ((s - 1) & 1) { DP_CORE(cA1, cB1, act); }
            else             { DP_CORE(cA0, cB0, act); }
        }
    }

    if (lane == t_lane) out[b] = D[k_t] + (float)(xl + yl);
}

extern "C" void kernel_launch(void* const* d_in, const int* in_sizes, int n_in,
                              void* d_out, int out_size) {
    const float* P    = (const float*)d_in[0];
    const int*   xs   = (const int*)d_in[1];
    const int*   ys   = (const int*)d_in[2];
    const int*   xlen = (const int*)d_in[3];
    const int*   ylen = (const int*)d_in[4];
    float*       out  = (float*)d_out;

    softmax_neg_kernel<<<S_DIM, 32>>>(P);
    build_kernel<<<B_DIM, 256>>>(xs, ys, xlen);
    dp_kernel<<<B_DIM, 32>>>(xlen, ylen, out);
}